// round 6
// baseline (speedup 1.0000x reference)
#include <cuda_runtime.h>
#include <math_constants.h>

// Problem constants
#define NPOS 65536   // 64 * 32 * 32 positions
#define DIM  64      // embedding dim
#define KCB  512     // codebook size
#define NCHW_ELEMS 4194304  // 64*64*32*32

typedef unsigned long long ull;

// Scratch (allocation-free: __device__ globals)
__device__ int   g_idx[NPOS];
__device__ int   g_hist[KCB];
__device__ float g_ne[KCB];        // ||e_k||^2 in fp32
__device__ float g_partial[512];

// Packed fp32x2 FMA (Blackwell): per-lane IEEE identical to scalar fmaf.
__device__ __forceinline__ void ffma2(ull& acc, ull a, ull b) {
    asm("fma.rn.f32x2 %0, %1, %2, %0;" : "+l"(acc) : "l"(a), "l"(b));
}
__device__ __forceinline__ ull dup2(float v) {
    ull r;
    asm("mov.b64 %0, {%1, %1};" : "=l"(r) : "f"(v));
    return r;
}
__device__ __forceinline__ void unpack2(ull p, float& lo, float& hi) {
    asm("mov.b64 {%0, %1}, %2;" : "=f"(lo), "=f"(hi) : "l"(p));
}

// ---------------------------------------------------------------------------
// Kernel 0: init — zero histogram, precompute ||e_k||^2 (fp32 fma chain)
// ---------------------------------------------------------------------------
__global__ void vq_init_kernel(const float* __restrict__ emb) {
    int t = threadIdx.x;
    if (t < KCB) {
        g_hist[t] = 0;
        const float4* e4 = (const float4*)(emb + t * DIM);
        float s = 0.f;
#pragma unroll
        for (int j = 0; j < 16; ++j) {
            float4 v = e4[j];
            s = fmaf(v.x, v.x, s);
            s = fmaf(v.y, v.y, s);
            s = fmaf(v.z, v.z, s);
            s = fmaf(v.w, v.w, s);
        }
        g_ne[t] = s;
    }
}

// ---------------------------------------------------------------------------
// Kernel A: argmin via tiled fp32 GEMM (FFMA2) + EMULATED reference rounding:
// dist = fl32(fl32(nx+ne) - fl32(2*s)), first-index argmin.
// Grid: 512 blocks x 256 threads. Block = 128 positions x 512 codes,
// 8 chunks of 64 codes, software-pipelined E fill (regs hide LDG latency).
// Es transposed [d][code]: mainloop e-loads immediate-offset, bank=lane.
// Warp ry: positions ry*16..ry*16+15 (paired into f32x2 lanes).
// Lane cx: codes ch*64 + cx, ch*64 + cx + 32.
// Issue/warp-d: 2 LDS + 4 MOV + 4 LDS.128 + 16 FFMA2 = 26 slots / 32 FMA-cyc.
// Crossbar: 6 wf / 32 FMA-cyc -> 0.75 of 128B/cyc at 4 warps/SMSP.
// ---------------------------------------------------------------------------
__global__ __launch_bounds__(256, 2) void vq_argmin_kernel(
    const float* __restrict__ x, const float* __restrict__ emb)
{
    __shared__ float Xs[64 * 128];   // [d][pos], 32 KB (pos pairs adjacent)
    __shared__ float Es[64 * 64];    // [d][code], 16 KB (total = 48 KB exactly)

    const int tid = threadIdx.x;
    const int posBase = blockIdx.x * 128;
    const int b  = posBase >> 10;       // 1024 positions per batch image
    const int hw = posBase & 1023;
    const float* xb = x + (size_t)b * 65536 + hw;  // + d*1024 + p

    // Load X tile (float4, coalesced): Xs[d*128+p]
#pragma unroll
    for (int it = 0; it < 8; ++it) {
        int j = it * 1024 + tid * 4;
        int d = j >> 7, p = j & 127;
        *(float4*)&Xs[d * 128 + p] = *(const float4*)&xb[d * 1024 + p];
    }

    // E prefetch for chunk 0: one code per lane, 16 d's (4 float4, regs)
    const int cc = tid & 63;            // code within chunk
    const int dg = (tid >> 6) * 16;     // d-group base
    float4 pre[4];
#pragma unroll
    for (int i = 0; i < 4; ++i)
        pre[i] = *(const float4*)&emb[cc * DIM + dg + 4 * i];

    __syncthreads();

    // nx per position, kept in registers: thread pair (2p,2p+1) computes xn[p]
    float myxn;
    {
        int p2 = tid >> 1, h = tid & 1;
        float s = 0.f;
#pragma unroll
        for (int j = 0; j < 32; ++j) {
            float v = Xs[(h * 32 + j) * 128 + p2];
            s = fmaf(v, v, s);
        }
        s += __shfl_xor_sync(0xffffffffu, s, 1);
        myxn = s;   // xn of position (tid>>1); any fp32 in right binade works
    }

    const int ry = tid >> 5;
    const int cx = tid & 31;

    float best[16];
    int   bidx[16];
#pragma unroll
    for (int i = 0; i < 16; ++i) { best[i] = CUDART_INF_F; bidx[i] = 0; }

    for (int ch = 0; ch < 8; ++ch) {
        __syncthreads();   // prior chunk's Es consumers done
        // Store prefetched E transposed: Es[d][cc]; banks = cc -> conflict-free
#pragma unroll
        for (int i = 0; i < 4; ++i) {
            Es[(dg + 4 * i + 0) * 64 + cc] = pre[i].x;
            Es[(dg + 4 * i + 1) * 64 + cc] = pre[i].y;
            Es[(dg + 4 * i + 2) * 64 + cc] = pre[i].z;
            Es[(dg + 4 * i + 3) * 64 + cc] = pre[i].w;
        }
        if (ch < 7) {
#pragma unroll
            for (int i = 0; i < 4; ++i)
                pre[i] = *(const float4*)&emb[((ch + 1) * 64 + cc) * DIM + dg + 4 * i];
        }
        __syncthreads();

        // acc[c][j]: code c in {cx, cx+32}, position pair j (pos 2j,2j+1)
        ull acc[2][8];
#pragma unroll
        for (int c = 0; c < 2; ++c)
#pragma unroll
            for (int j = 0; j < 8; ++j) acc[c][j] = 0ull;

#pragma unroll 8
        for (int d = 0; d < 64; ++d) {
            ull e0 = dup2(Es[d * 64 + cx]);        // bank = cx: conflict-free
            ull e1 = dup2(Es[d * 64 + cx + 32]);
            const float* xr = &Xs[d * 128 + ry * 16];   // warp-uniform: broadcast
            const ulonglong2 a0 = *(const ulonglong2*)(xr);
            const ulonglong2 a1 = *(const ulonglong2*)(xr + 4);
            const ulonglong2 a2 = *(const ulonglong2*)(xr + 8);
            const ulonglong2 a3 = *(const ulonglong2*)(xr + 12);
            ffma2(acc[0][0], a0.x, e0); ffma2(acc[0][1], a0.y, e0);
            ffma2(acc[0][2], a1.x, e0); ffma2(acc[0][3], a1.y, e0);
            ffma2(acc[0][4], a2.x, e0); ffma2(acc[0][5], a2.y, e0);
            ffma2(acc[0][6], a3.x, e0); ffma2(acc[0][7], a3.y, e0);
            ffma2(acc[1][0], a0.x, e1); ffma2(acc[1][1], a0.y, e1);
            ffma2(acc[1][2], a1.x, e1); ffma2(acc[1][3], a1.y, e1);
            ffma2(acc[1][4], a2.x, e1); ffma2(acc[1][5], a2.y, e1);
            ffma2(acc[1][6], a3.x, e1); ffma2(acc[1][7], a3.y, e1);
        }

        // Epilogue: emulate jax rounding, running first-index argmin.
        const int k0 = ch * 64 + cx;
        const int k1 = k0 + 32;
        const float ne0 = __ldg(&g_ne[k0]);
        const float ne1 = __ldg(&g_ne[k1]);
#pragma unroll
        for (int j = 0; j < 8; ++j) {
            float nxa = __shfl_sync(0xffffffffu, myxn, 4 * j);      // pos 2j
            float nxb = __shfl_sync(0xffffffffu, myxn, 4 * j + 2);  // pos 2j+1
            float s0a, s0b, s1a, s1b;
            unpack2(acc[0][j], s0a, s0b);
            unpack2(acc[1][j], s1a, s1b);
            float d0a = __fsub_rn(__fadd_rn(nxa, ne0), __fmul_rn(2.0f, s0a));
            float d1a = __fsub_rn(__fadd_rn(nxa, ne1), __fmul_rn(2.0f, s1a));
            float d0b = __fsub_rn(__fadd_rn(nxb, ne0), __fmul_rn(2.0f, s0b));
            float d1b = __fsub_rn(__fadd_rn(nxb, ne1), __fmul_rn(2.0f, s1b));
            if (d0a < best[2 * j])     { best[2 * j]     = d0a; bidx[2 * j]     = k0; }
            if (d1a < best[2 * j])     { best[2 * j]     = d1a; bidx[2 * j]     = k1; }
            if (d0b < best[2 * j + 1]) { best[2 * j + 1] = d0b; bidx[2 * j + 1] = k0; }
            if (d1b < best[2 * j + 1]) { best[2 * j + 1] = d1b; bidx[2 * j + 1] = k1; }
        }
    }

    // Warp butterfly argmin per position (tie -> smaller index)
#pragma unroll
    for (int i = 0; i < 16; ++i) {
        float v = best[i];
        int   id = bidx[i];
#pragma unroll
        for (int off = 16; off > 0; off >>= 1) {
            float ov = __shfl_xor_sync(0xffffffffu, v, off);
            int   oi = __shfl_xor_sync(0xffffffffu, id, off);
            if (ov < v || (ov == v && oi < id)) { v = ov; id = oi; }
        }
        if (cx == 0) {
            int pos = posBase + ry * 16 + i;
            g_idx[pos] = id;
            atomicAdd(&g_hist[id], 1);
        }
    }
}

// ---------------------------------------------------------------------------
// Kernel B: gather + straight-through emulation + both layouts + loss partials.
// q_st = fl32(x + fl32(q - x)).
// Output layout: out[0]=loss, out[1..]=NCHW q_st, out[1+N]=perplexity,
//                out[2+N..]=flat NHWC q_st.
// ---------------------------------------------------------------------------
__global__ __launch_bounds__(256) void vq_output_kernel(
    const float* __restrict__ x, const float* __restrict__ emb,
    float* __restrict__ out)
{
    __shared__ float qs[128 * 65];   // tile [pos][d], pad 65
    __shared__ int   ks[128];
    __shared__ float red[256];

    const int tid = threadIdx.x;
    const int posBase = blockIdx.x * 128;
    const int b  = posBase >> 10;
    const int hw = posBase & 1023;

    if (tid < 128) ks[tid] = g_idx[posBase + tid];
    __syncthreads();

    float* out_nchw = out + 1;
    float* out_flat = out + 2 + NCHW_ELEMS;

    // Pass 1 (pos-major): coalesced codebook gather into smem
#pragma unroll
    for (int it = 0; it < 32; ++it) {
        int j = it * 256 + tid;
        int p = j >> 6, d = j & 63;
        qs[p * 65 + d] = emb[ks[p] * DIM + d];
    }
    __syncthreads();

    // Pass 2 (d-major): coalesced x read, NCHW q_st write, loss accumulation
    float lsum = 0.f;
#pragma unroll
    for (int it = 0; it < 32; ++it) {
        int j = it * 256 + tid;
        int d = j >> 7, p = j & 127;
        size_t g = (size_t)b * 65536 + (size_t)d * 1024 + hw + p;
        float q  = qs[p * 65 + d];
        float xv = x[g];
        float df  = __fsub_rn(q, xv);       // fl32(q - x)
        float qst = __fadd_rn(xv, df);      // fl32(x + (q - x))
        out_nchw[g] = qst;
        qs[p * 65 + d] = qst;
        lsum = fmaf(df, df, lsum);
    }
    __syncthreads();

    // Pass 3 (pos-major): flat NHWC q_st write (coalesced)
#pragma unroll
    for (int it = 0; it < 32; ++it) {
        int j = it * 256 + tid;
        int p = j >> 6, d = j & 63;
        out_flat[(size_t)(posBase + p) * DIM + d] = qs[p * 65 + d];
    }

    red[tid] = lsum;
    __syncthreads();
    for (int s = 128; s > 0; s >>= 1) {
        if (tid < s) red[tid] += red[tid + s];
        __syncthreads();
    }
    if (tid == 0) g_partial[blockIdx.x] = red[0];
}

// ---------------------------------------------------------------------------
// Kernel C: deterministic finalize — loss scalar + perplexity (all fp32).
// ---------------------------------------------------------------------------
__global__ void vq_finalize_kernel(float* __restrict__ out) {
    __shared__ float red[512];
    const int t = threadIdx.x;

    red[t] = g_partial[t];
    __syncthreads();
    for (int s = 256; s > 0; s >>= 1) {
        if (t < s) red[t] += red[t + s];
        __syncthreads();
    }
    if (t == 0) {
        out[0] = 1.25f * (red[0] / (float)NCHW_ELEMS);
    }
    __syncthreads();

    float p = (float)g_hist[t] * (1.0f / 65536.0f);
    red[t] = p * logf(p + 1e-10f);
    __syncthreads();
    for (int s = 256; s > 0; s >>= 1) {
        if (t < s) red[t] += red[t + s];
        __syncthreads();
    }
    if (t == 0) {
        out[NCHW_ELEMS + 1] = expf(-red[0]);
    }
}

// ---------------------------------------------------------------------------
extern "C" void kernel_launch(void* const* d_in, const int* in_sizes, int n_in,
                              void* d_out, int out_size) {
    const float* x   = (const float*)d_in[0];   // [64,64,32,32] f32 NCHW
    const float* emb = (const float*)d_in[1];   // [512,64] f32
    float* out = (float*)d_out;

    vq_init_kernel<<<1, 512>>>(emb);
    vq_argmin_kernel<<<512, 256>>>(x, emb);
    vq_output_kernel<<<512, 256>>>(x, emb, out);
    vq_finalize_kernel<<<1, 512>>>(out);
}

// round 7
// speedup vs baseline: 1.2378x; 1.2378x over previous
#include <cuda_runtime.h>
#include <math_constants.h>

// Problem constants
#define NPOS 65536   // 64 * 32 * 32 positions
#define DIM  64      // embedding dim
#define KCB  512     // codebook size
#define NCHW_ELEMS 4194304  // 64*64*32*32

typedef unsigned long long ull;

// Scratch (allocation-free: __device__ globals)
__device__ int   g_hist[KCB];
__device__ float g_ne[KCB];        // ||e_k||^2 in fp32
__device__ float g_partial[512];

// Packed fp32x2 FMA (Blackwell): per-lane IEEE identical to scalar fmaf.
__device__ __forceinline__ void ffma2(ull& acc, ull a, ull b) {
    asm("fma.rn.f32x2 %0, %1, %2, %0;" : "+l"(acc) : "l"(a), "l"(b));
}
__device__ __forceinline__ ull dup2(float v) {
    ull r;
    asm("mov.b64 %0, {%1, %1};" : "=l"(r) : "f"(v));
    return r;
}
__device__ __forceinline__ void unpack2(ull p, float& lo, float& hi) {
    asm("mov.b64 {%0, %1}, %2;" : "=f"(lo), "=f"(hi) : "l"(p));
}

// ---------------------------------------------------------------------------
// Kernel 0: init — zero histogram, precompute ||e_k||^2 (fp32 fma chain)
// ---------------------------------------------------------------------------
__global__ void vq_init_kernel(const float* __restrict__ emb) {
    int t = threadIdx.x;
    if (t < KCB) {
        g_hist[t] = 0;
        const float4* e4 = (const float4*)(emb + t * DIM);
        float s = 0.f;
#pragma unroll
        for (int j = 0; j < 16; ++j) {
            float4 v = e4[j];
            s = fmaf(v.x, v.x, s);
            s = fmaf(v.y, v.y, s);
            s = fmaf(v.z, v.z, s);
            s = fmaf(v.w, v.w, s);
        }
        g_ne[t] = s;
    }
}

// ---------------------------------------------------------------------------
// Fused kernel: argmin GEMM (R5's proven per-thread shape, 2 X-tiles per
// E-chunk load) + gather + straight-through + both output layouts + loss.
// dist = fl32(fl32(nx+ne) - fl32(2*s)), first-index argmin (jax emulation).
// Grid: 512 blocks x 256 threads. Block = 128 positions x 512 codes.
// Per (chunk, xtile): warp ry covers positions xt*64 + ry*8 .. +7 (f32x2
// pairs); lane cx covers codes ch*128 + cx + {0,32,64,96}. acc[4][4] reused.
// After argmin: Es buffer reused as qs[128][65] for the output passes; x
// comes from the already-resident Xs tile (no global re-read).
// ---------------------------------------------------------------------------
__global__ __launch_bounds__(256, 2) void vq_fused_kernel(
    const float* __restrict__ x, const float* __restrict__ emb,
    float* __restrict__ out)
{
    __shared__ float Xs[64 * 128];    // [d][pos], 32 KB (pos pairs adjacent)
    __shared__ float Es[128 * 65];    // [code][d] pad 65; reused as qs[pos][d]
    __shared__ float nes[KCB];        // ||e_k||^2 staged
    __shared__ float xpart[4 * 128];  // nx partials; reused as loss red[256]
    __shared__ float xn[128];         // ||x_p||^2 (R5-identical bits)
    __shared__ int   widx[128];       // winning code per position

    const int tid = threadIdx.x;
    const int posBase = blockIdx.x * 128;
    const int b  = posBase >> 10;       // 1024 positions per batch image
    const int hw = posBase & 1023;
    const float* xb = x + (size_t)b * 65536 + hw;  // + d*1024 + p

    // Load X tile (float4, coalesced): Xs[d*128+p], 64 d x 128 p
#pragma unroll
    for (int it = 0; it < 8; ++it) {
        int j = it * 1024 + tid * 4;
        int d = j >> 7, p = j & 127;
        *(float4*)&Xs[d * 128 + p] = *(const float4*)&xb[d * 1024 + p];
    }
    // Stage ne
    nes[tid] = g_ne[tid];
    nes[tid + 256] = g_ne[tid + 256];
    __syncthreads();

    // nx per position — EXACT R5 grouping: 4 fma-chains of 16 d's, combined
    // ((p0+p1)+p2)+p3. (nx low bits shift fl(nx+ne) boundaries; keep bitwise.)
    {
        int p = tid & 127;
        int g0 = tid >> 7;              // 0 or 1; this thread does g0 and g0+2
        float s0 = 0.f, s2 = 0.f;
#pragma unroll
        for (int j = 0; j < 16; ++j)
            s0 = fmaf(Xs[(g0 * 16 + j) * 128 + p], Xs[(g0 * 16 + j) * 128 + p], s0);
#pragma unroll
        for (int j = 0; j < 16; ++j)
            s2 = fmaf(Xs[((g0 + 2) * 16 + j) * 128 + p], Xs[((g0 + 2) * 16 + j) * 128 + p], s2);
        xpart[g0 * 128 + p] = s0;
        xpart[(g0 + 2) * 128 + p] = s2;
    }
    __syncthreads();
    if (tid < 128) {
        xn[tid] = ((xpart[tid] + xpart[128 + tid]) + xpart[256 + tid]) + xpart[384 + tid];
    }
    // (next __syncthreads below publishes xn before first epilogue use)

    const int ry = tid >> 5;
    const int cx = tid & 31;

    float best[16];
    int   bidx[16];
#pragma unroll
    for (int i = 0; i < 16; ++i) { best[i] = CUDART_INF_F; bidx[i] = 0; }

    for (int ch = 0; ch < 4; ++ch) {
        __syncthreads();
        // Load E chunk (128 codes x 64 d), scalar stores (R5 pattern)
#pragma unroll
        for (int it = 0; it < 8; ++it) {
            int j  = it * 1024 + tid * 4;
            int cc = j >> 6, d = j & 63;
            float4 e4 = *(const float4*)&emb[(ch * 128 + cc) * DIM + d];
            float* row = &Es[cc * 65 + d];
            row[0] = e4.x; row[1] = e4.y; row[2] = e4.z; row[3] = e4.w;
        }
        __syncthreads();

#pragma unroll
        for (int xt = 0; xt < 2; ++xt) {
            // acc[g][j]: code group g (k = ch*128+cx+32g), position pair j
            ull acc[4][4];
#pragma unroll
            for (int g = 0; g < 4; ++g)
#pragma unroll
                for (int j = 0; j < 4; ++j) acc[g][j] = 0ull;

#pragma unroll 16
            for (int d = 0; d < 64; ++d) {
                // scalar e loads: bank = (cx + d) % 32 -> conflict-free
                ull e0 = dup2(Es[(cx      ) * 65 + d]);
                ull e1 = dup2(Es[(cx + 32 ) * 65 + d]);
                ull e2 = dup2(Es[(cx + 64 ) * 65 + d]);
                ull e3 = dup2(Es[(cx + 96 ) * 65 + d]);
                // broadcast 128-bit shared loads: 4 packed position-pairs
                const float* xr = &Xs[d * 128 + xt * 64 + ry * 8];
                const ulonglong2 a0 = *(const ulonglong2*)(xr);
                const ulonglong2 a1 = *(const ulonglong2*)(xr + 4);
                ffma2(acc[0][0], a0.x, e0); ffma2(acc[0][1], a0.y, e0);
                ffma2(acc[0][2], a1.x, e0); ffma2(acc[0][3], a1.y, e0);
                ffma2(acc[1][0], a0.x, e1); ffma2(acc[1][1], a0.y, e1);
                ffma2(acc[1][2], a1.x, e1); ffma2(acc[1][3], a1.y, e1);
                ffma2(acc[2][0], a0.x, e2); ffma2(acc[2][1], a0.y, e2);
                ffma2(acc[2][2], a1.x, e2); ffma2(acc[2][3], a1.y, e2);
                ffma2(acc[3][0], a0.x, e3); ffma2(acc[3][1], a0.y, e3);
                ffma2(acc[3][2], a1.x, e3); ffma2(acc[3][3], a1.y, e3);
            }

            // Epilogue: emulate jax rounding, running first-index argmin.
            // g ascending => code index ascending within thread.
#pragma unroll
            for (int g = 0; g < 4; ++g) {
                const int k = ch * 128 + cx + g * 32;
                const float ne = nes[k];
#pragma unroll
                for (int j = 0; j < 4; ++j) {
                    float sa, sb;
                    unpack2(acc[g][j], sa, sb);
                    float nxa = xn[xt * 64 + ry * 8 + 2 * j];
                    float nxb = xn[xt * 64 + ry * 8 + 2 * j + 1];
                    float da = __fsub_rn(__fadd_rn(nxa, ne), __fmul_rn(2.0f, sa));
                    float db = __fsub_rn(__fadd_rn(nxb, ne), __fmul_rn(2.0f, sb));
                    int ii = xt * 8 + 2 * j;
                    if (da < best[ii])     { best[ii]     = da; bidx[ii]     = k; }
                    if (db < best[ii + 1]) { best[ii + 1] = db; bidx[ii + 1] = k; }
                }
            }
        }
    }

    // Warp butterfly argmin per position (tie -> smaller index)
#pragma unroll
    for (int i = 0; i < 16; ++i) {
        float v = best[i];
        int   id = bidx[i];
#pragma unroll
        for (int off = 16; off > 0; off >>= 1) {
            float ov = __shfl_xor_sync(0xffffffffu, v, off);
            int   oi = __shfl_xor_sync(0xffffffffu, id, off);
            if (ov < v || (ov == v && oi < id)) { v = ov; id = oi; }
        }
        if (cx == 0) {
            int pl = (i >> 3) * 64 + ry * 8 + (i & 7);   // local position
            widx[pl] = id;
            atomicAdd(&g_hist[id], 1);
        }
    }
    __syncthreads();

    // ---------------- fused output (Es reused as qs[128][65]) ----------------
    float* out_nchw = out + 1;
    float* out_flat = out + 2 + NCHW_ELEMS;

    // Pass 1 (pos-major): coalesced codebook gather into qs
#pragma unroll
    for (int it = 0; it < 32; ++it) {
        int j = it * 256 + tid;
        int p = j >> 6, d = j & 63;
        Es[p * 65 + d] = emb[widx[p] * DIM + d];
    }
    __syncthreads();

    // Pass 2 (d-major): x from resident Xs, NCHW q_st write, loss accumulation
    // (identical per-thread fma chain to the former output kernel)
    float lsum = 0.f;
#pragma unroll
    for (int it = 0; it < 32; ++it) {
        int j = it * 256 + tid;
        int d = j >> 7, p = j & 127;
        size_t g = (size_t)b * 65536 + (size_t)d * 1024 + hw + p;
        float q  = Es[p * 65 + d];
        float xv = Xs[d * 128 + p];
        float df  = __fsub_rn(q, xv);       // fl32(q - x)
        float qst = __fadd_rn(xv, df);      // fl32(x + (q - x))
        out_nchw[g] = qst;
        Es[p * 65 + d] = qst;
        lsum = fmaf(df, df, lsum);
    }
    __syncthreads();

    // Pass 3 (pos-major): flat NHWC q_st write (coalesced)
#pragma unroll
    for (int it = 0; it < 32; ++it) {
        int j = it * 256 + tid;
        int p = j >> 6, d = j & 63;
        out_flat[(size_t)(posBase + p) * DIM + d] = Es[p * 65 + d];
    }

    // Loss partial (tree identical to former output kernel); reuse xpart
    float* red = xpart;
    red[tid] = lsum;
    __syncthreads();
    for (int s = 128; s > 0; s >>= 1) {
        if (tid < s) red[tid] += red[tid + s];
        __syncthreads();
    }
    if (tid == 0) g_partial[blockIdx.x] = red[0];
}

// ---------------------------------------------------------------------------
// Finalize: deterministic loss scalar + perplexity (all fp32).
// ---------------------------------------------------------------------------
__global__ void vq_finalize_kernel(float* __restrict__ out) {
    __shared__ float red[512];
    const int t = threadIdx.x;

    red[t] = g_partial[t];
    __syncthreads();
    for (int s = 256; s > 0; s >>= 1) {
        if (t < s) red[t] += red[t + s];
        __syncthreads();
    }
    if (t == 0) {
        out[0] = 1.25f * (red[0] / (float)NCHW_ELEMS);
    }
    __syncthreads();

    float p = (float)g_hist[t] * (1.0f / 65536.0f);
    red[t] = p * logf(p + 1e-10f);
    __syncthreads();
    for (int s = 256; s > 0; s >>= 1) {
        if (t < s) red[t] += red[t + s];
        __syncthreads();
    }
    if (t == 0) {
        out[NCHW_ELEMS + 1] = expf(-red[0]);
    }
}

// ---------------------------------------------------------------------------
extern "C" void kernel_launch(void* const* d_in, const int* in_sizes, int n_in,
                              void* d_out, int out_size) {
    const float* x   = (const float*)d_in[0];   // [64,64,32,32] f32 NCHW
    const float* emb = (const float*)d_in[1];   // [512,64] f32
    float* out = (float*)d_out;

    vq_init_kernel<<<1, 512>>>(emb);
    vq_fused_kernel<<<512, 256>>>(x, emb, out);
    vq_finalize_kernel<<<1, 512>>>(out);
}